// round 2
// baseline (speedup 1.0000x reference)
#include <cuda_runtime.h>

#define BB 8
#define NN 2048
#define DD 128
#define K_TOP 8
#define TILE 128
#define NT 16            // NN / TILE
#define PADB 132
#define PADC 132
#define NEG_INF (-3.402823466e38f)

// scratch (no allocations allowed)
__device__ float g_normed[BB * NN * DD];                 // 8 MB
__device__ float g_pval[BB * NN * NT * K_TOP];           // 8 MB
__device__ int   g_pidx[BB * NN * NT * K_TOP];           // 8 MB

// ---------------------------------------------------------------------------
// 1) L2 normalize: one warp per row of 128 floats
// ---------------------------------------------------------------------------
__global__ void normalize_kernel(const float* __restrict__ x) {
    int row  = (blockIdx.x * blockDim.x + threadIdx.x) >> 5;
    int lane = threadIdx.x & 31;
    if (row >= BB * NN) return;
    const float4* src = (const float4*)(x + (size_t)row * DD);
    float4 v = src[lane];
    float s = v.x * v.x + v.y * v.y + v.z * v.z + v.w * v.w;
    #pragma unroll
    for (int off = 16; off; off >>= 1) s += __shfl_xor_sync(0xffffffffu, s, off);
    float nrm = fmaxf(sqrtf(s), 1e-12f);
    float4 o = make_float4(v.x / nrm, v.y / nrm, v.z / nrm, v.w / nrm);
    ((float4*)(g_normed + (size_t)row * DD))[lane] = o;
}

// ---------------------------------------------------------------------------
// 2) zero the (poisoned) output
// ---------------------------------------------------------------------------
__global__ void zero_kernel(float4* __restrict__ out, int n4) {
    int i = blockIdx.x * blockDim.x + threadIdx.x;
    int stride = gridDim.x * blockDim.x;
    float4 z = make_float4(0.f, 0.f, 0.f, 0.f);
    for (; i < n4; i += stride) out[i] = z;
}

// ---------------------------------------------------------------------------
// 3) symmetric 128x128x128 fp32 GEMM tile + per-row / per-col partial top-8
//    grid: (NT*(NT+1)/2, BB), 256 threads, dyn smem = (128*128 + 128*132)*4 B
// ---------------------------------------------------------------------------
__global__ void __launch_bounds__(256) gemm_topk_kernel() {
    extern __shared__ float smem[];
    float* As = smem;               // [128][128]   rows of I-tile, row-major
    float* Bs = smem + TILE * DD;   // [128][PADB]  rows of J-tile, row-major
    float* Cs = smem;               // [128][PADC]  scores, overlays As + 2KB of Bs

    int b = blockIdx.y;
    int p = blockIdx.x;
    int I = 0;
    while (p >= NT - I) { p -= NT - I; I++; }
    int J = I + p;

    int tid = threadIdx.x;
    const float* Abase = g_normed + ((size_t)b * NN + (size_t)I * TILE) * DD;
    const float* Bbase = g_normed + ((size_t)b * NN + (size_t)J * TILE) * DD;

    // cooperative tile load: each tile is a contiguous 64KB slab (coalesced)
    #pragma unroll
    for (int i = 0; i < 16; i++) {
        int f  = tid + i * 256;      // float4 index within tile
        int r  = f >> 5;             // 32 float4 per row
        int k4 = f & 31;
        float4 va = ((const float4*)Abase)[f];
        *(float4*)&As[r * DD + k4 * 4] = va;
        float4 vb = ((const float4*)Bbase)[f];
        *(float4*)&Bs[r * PADB + k4 * 4] = vb;
    }
    __syncthreads();

    // 8x8 micro-tile, strided mapping: rows ty+16i, cols tx+16j
    int tx = tid & 15, ty = tid >> 4;
    float acc[8][8];
    #pragma unroll
    for (int i = 0; i < 8; i++)
        #pragma unroll
        for (int j = 0; j < 8; j++) acc[i][j] = 0.f;

    #pragma unroll 4
    for (int k4 = 0; k4 < 32; k4++) {
        float4 a4[8], b4[8];
        #pragma unroll
        for (int i = 0; i < 8; i++)
            a4[i] = *(const float4*)&As[(ty + 16 * i) * DD + k4 * 4];
        #pragma unroll
        for (int j = 0; j < 8; j++)
            b4[j] = *(const float4*)&Bs[(tx + 16 * j) * PADB + k4 * 4];
        #pragma unroll
        for (int i = 0; i < 8; i++)
            #pragma unroll
            for (int j = 0; j < 8; j++) {
                acc[i][j] += a4[i].x * b4[j].x;
                acc[i][j] += a4[i].y * b4[j].y;
                acc[i][j] += a4[i].z * b4[j].z;
                acc[i][j] += a4[i].w * b4[j].w;
            }
    }

    __syncthreads();   // Cs overlaps Bs head: wait for all k-loop reads
    #pragma unroll
    for (int i = 0; i < 8; i++)
        #pragma unroll
        for (int j = 0; j < 8; j++)
            Cs[(ty + 16 * i) * PADC + (tx + 16 * j)] = acc[i][j];
    __syncthreads();

    int lane = tid & 31, w = tid >> 5;

    // --- row pass: top-8 per I-row over J-columns -> slot J ---
    for (int rr = w; rr < TILE; rr += 8) {
        float v[4];
        #pragma unroll
        for (int q = 0; q < 4; q++) v[q] = Cs[rr * PADC + lane + 32 * q];
        size_t grow = (size_t)b * NN + (size_t)I * TILE + rr;
        float* pv = g_pval + (grow * NT + J) * K_TOP;
        int*   pi = g_pidx + (grow * NT + J) * K_TOP;
        #pragma unroll
        for (int t = 0; t < K_TOP; t++) {
            float bv = v[0]; int bc = lane;
            #pragma unroll
            for (int q = 1; q < 4; q++) {
                int c = lane + 32 * q;
                if (v[q] > bv || (v[q] == bv && c < bc)) { bv = v[q]; bc = c; }
            }
            #pragma unroll
            for (int off = 16; off; off >>= 1) {
                float ov = __shfl_xor_sync(0xffffffffu, bv, off);
                int   oc = __shfl_xor_sync(0xffffffffu, bc, off);
                if (ov > bv || (ov == bv && oc < bc)) { bv = ov; bc = oc; }
            }
            if (lane == 0) { pv[t] = bv; pi[t] = J * TILE + bc; }
            if ((bc & 31) == lane) v[bc >> 5] = NEG_INF;
        }
    }

    // --- col pass (off-diagonal only): top-8 per J-row over I-columns -> slot I
    if (I != J) {
        for (int cc = w; cc < TILE; cc += 8) {
            float v[4];
            #pragma unroll
            for (int q = 0; q < 4; q++) v[q] = Cs[(lane + 32 * q) * PADC + cc];
            size_t grow = (size_t)b * NN + (size_t)J * TILE + cc;
            float* pv = g_pval + (grow * NT + I) * K_TOP;
            int*   pi = g_pidx + (grow * NT + I) * K_TOP;
            #pragma unroll
            for (int t = 0; t < K_TOP; t++) {
                float bv = v[0]; int br = lane;
                #pragma unroll
                for (int q = 1; q < 4; q++) {
                    int r = lane + 32 * q;
                    if (v[q] > bv || (v[q] == bv && r < br)) { bv = v[q]; br = r; }
                }
                #pragma unroll
                for (int off = 16; off; off >>= 1) {
                    float ov = __shfl_xor_sync(0xffffffffu, bv, off);
                    int   orr = __shfl_xor_sync(0xffffffffu, br, off);
                    if (ov > bv || (ov == bv && orr < br)) { bv = ov; br = orr; }
                }
                if (lane == 0) { pv[t] = bv; pi[t] = I * TILE + br; }
                if ((br & 31) == lane) v[br >> 5] = NEG_INF;
            }
        }
    }
}

// ---------------------------------------------------------------------------
// 4) merge 16 partial top-8 lists per row -> global top-8, scatter adjacency
//    one warp per row
// ---------------------------------------------------------------------------
__global__ void merge_scatter_kernel(float* __restrict__ out) {
    int gw   = (blockIdx.x * blockDim.x + threadIdx.x) >> 5;
    int lane = threadIdx.x & 31;
    if (gw >= BB * NN) return;
    int b = gw / NN, n = gw % NN;
    const float* pv = g_pval + (size_t)gw * NT * K_TOP;
    const int*   pi = g_pidx + (size_t)gw * NT * K_TOP;
    float v[4]; int id[4];
    #pragma unroll
    for (int q = 0; q < 4; q++) {
        v[q]  = pv[lane + 32 * q];
        id[q] = pi[lane + 32 * q];
    }
    float* base = out + (size_t)b * NN * NN;
    #pragma unroll
    for (int t = 0; t < K_TOP; t++) {
        float bv = v[0]; int bi = id[0];
        #pragma unroll
        for (int q = 1; q < 4; q++)
            if (v[q] > bv || (v[q] == bv && id[q] < bi)) { bv = v[q]; bi = id[q]; }
        #pragma unroll
        for (int off = 16; off; off >>= 1) {
            float ov = __shfl_xor_sync(0xffffffffu, bv, off);
            int   oi = __shfl_xor_sync(0xffffffffu, bi, off);
            if (ov > bv || (ov == bv && oi < bi)) { bv = ov; bi = oi; }
        }
        if (lane == t) {
            base[(size_t)n * NN + bi] = 1.0f;   // adj[n, idx]
            base[(size_t)bi * NN + n] = 1.0f;   // adj[idx, n] (symmetrize)
        }
        #pragma unroll
        for (int q = 0; q < 4; q++)
            if (id[q] == bi) v[q] = NEG_INF;    // indices are unique
    }
    if (lane == 8) base[(size_t)n * NN + n] = 1.0f;  // self loop
}

// ---------------------------------------------------------------------------
extern "C" void kernel_launch(void* const* d_in, const int* in_sizes, int n_in,
                              void* d_out, int out_size) {
    const float* x = (const float*)d_in[0];
    float* out = (float*)d_out;

    size_t smem_bytes = (size_t)(TILE * DD + TILE * PADB) * sizeof(float); // 133120
    cudaFuncSetAttribute(gemm_topk_kernel,
                         cudaFuncAttributeMaxDynamicSharedMemorySize,
                         (int)smem_bytes);

    normalize_kernel<<<(BB * NN) / 8, 256>>>(x);
    zero_kernel<<<8192, 256>>>((float4*)out, out_size / 4);
    gemm_topk_kernel<<<dim3(NT * (NT + 1) / 2, BB), 256, smem_bytes>>>();
    merge_scatter_kernel<<<(BB * NN) / 8, 256>>>(out);
}

// round 4
// speedup vs baseline: 1.2924x; 1.2924x over previous
#include <cuda_runtime.h>
#include <cstdint>

#define BB 8
#define NN 2048
#define DD 128
#define K_TOP 8
#define TILE 128
#define NT 16
#define PAD 132
#define NEG_INF (-3.402823466e38f)

__device__ float g_normed[BB * NN * DD];
__device__ float g_pval[BB * NN * NT * K_TOP];
__device__ int   g_pidx[BB * NN * NT * K_TOP];

// ---------------------------------------------------------------------------
__global__ void normalize_kernel(const float* __restrict__ x) {
    int row  = (blockIdx.x * blockDim.x + threadIdx.x) >> 5;
    int lane = threadIdx.x & 31;
    if (row >= BB * NN) return;
    float4 v = ((const float4*)(x + (size_t)row * DD))[lane];
    float s = v.x * v.x + v.y * v.y + v.z * v.z + v.w * v.w;
    #pragma unroll
    for (int o = 16; o; o >>= 1) s += __shfl_xor_sync(0xffffffffu, s, o);
    float nrm = fmaxf(sqrtf(s), 1e-12f);
    float4 ov = make_float4(v.x / nrm, v.y / nrm, v.z / nrm, v.w / nrm);
    ((float4*)(g_normed + (size_t)row * DD))[lane] = ov;
}

__global__ void zero_kernel(float4* __restrict__ out, int n4) {
    int i = blockIdx.x * blockDim.x + threadIdx.x;
    int st = gridDim.x * blockDim.x;
    float4 z = make_float4(0.f, 0.f, 0.f, 0.f);
    for (; i < n4; i += st) out[i] = z;
}

// ---------------------------------------------------------------------------
__device__ __forceinline__ uint32_t f2tf32(float f) {
    uint32_t r;
    asm("cvt.rna.tf32.f32 %0, %1;" : "=r"(r) : "f"(f));
    return r;
}
__device__ __forceinline__ void mma8(float (&d)[4], const uint32_t (&a)[4],
                                     const uint32_t (&b)[2]) {
    asm volatile(
        "mma.sync.aligned.m16n8k8.row.col.f32.tf32.tf32.f32 "
        "{%0,%1,%2,%3}, {%4,%5,%6,%7}, {%8,%9}, {%0,%1,%2,%3};"
        : "+f"(d[0]), "+f"(d[1]), "+f"(d[2]), "+f"(d[3])
        : "r"(a[0]), "r"(a[1]), "r"(a[2]), "r"(a[3]), "r"(b[0]), "r"(b[1]));
}

// ---------------------------------------------------------------------------
// symmetric 128x128 tile: 3xTF32 mma.sync GEMM + fused partial top-8
// grid (136, 8), 512 threads, dyn smem = 2*128*132*4 = 135168
// ---------------------------------------------------------------------------
__global__ void __launch_bounds__(512, 1) gemm_topk_kernel() {
    extern __shared__ float smem[];
    float* As = smem;                 // [128][132]
    float* Bs = smem + TILE * PAD;    // [128][132]
    float* Cs = smem;                 // overlays As

    int b = blockIdx.y;
    int p = blockIdx.x;
    int I = 0;
    while (p >= NT - I) { p -= NT - I; I++; }
    int J = I + p;

    int tid = threadIdx.x;
    const float* Abase = g_normed + ((size_t)b * NN + (size_t)I * TILE) * DD;
    const float* Bbase = g_normed + ((size_t)b * NN + (size_t)J * TILE) * DD;

    #pragma unroll
    for (int i = 0; i < 8; i++) {
        int f = tid + i * 512;
        int r = f >> 5, k4 = f & 31;
        *(float4*)&As[r * PAD + k4 * 4] = ((const float4*)Abase)[f];
        *(float4*)&Bs[r * PAD + k4 * 4] = ((const float4*)Bbase)[f];
    }
    __syncthreads();

    int lane = tid & 31, w = tid >> 5;
    int lr = lane >> 2, lc = lane & 3;
    int wr = w & 3, wc = w >> 2;
    int mrow = wr * 32, ncol = wc * 32;

    float accA[2][4][4], accB[2][4][4];
    #pragma unroll
    for (int mt = 0; mt < 2; mt++)
        #pragma unroll
        for (int nt = 0; nt < 4; nt++)
            #pragma unroll
            for (int q = 0; q < 4; q++) { accA[mt][nt][q] = 0.f; accB[mt][nt][q] = 0.f; }

    #pragma unroll 2
    for (int ks = 0; ks < 16; ks++) {
        int k0 = ks * 8;
        uint32_t ah[2][4], am[2][4];
        #pragma unroll
        for (int mt = 0; mt < 2; mt++) {
            const float* ap = &As[(mrow + mt * 16 + lr) * PAD + k0 + lc];
            float x0 = ap[0];
            float x1 = ap[8 * PAD];
            float x2 = ap[4];
            float x3 = ap[8 * PAD + 4];
            ah[mt][0] = f2tf32(x0); am[mt][0] = f2tf32(x0 - __uint_as_float(ah[mt][0]));
            ah[mt][1] = f2tf32(x1); am[mt][1] = f2tf32(x1 - __uint_as_float(ah[mt][1]));
            ah[mt][2] = f2tf32(x2); am[mt][2] = f2tf32(x2 - __uint_as_float(ah[mt][2]));
            ah[mt][3] = f2tf32(x3); am[mt][3] = f2tf32(x3 - __uint_as_float(ah[mt][3]));
        }
        uint32_t bh[4][2], bm[4][2];
        #pragma unroll
        for (int nt = 0; nt < 4; nt++) {
            const float* bp = &Bs[(ncol + nt * 8 + lr) * PAD + k0 + lc];
            float y0 = bp[0];
            float y1 = bp[4];
            bh[nt][0] = f2tf32(y0); bm[nt][0] = f2tf32(y0 - __uint_as_float(bh[nt][0]));
            bh[nt][1] = f2tf32(y1); bm[nt][1] = f2tf32(y1 - __uint_as_float(bh[nt][1]));
        }
        #pragma unroll
        for (int mt = 0; mt < 2; mt++)
            #pragma unroll
            for (int nt = 0; nt < 4; nt++) {
                mma8(accA[mt][nt], ah[mt], bh[nt]);
                mma8(accB[mt][nt], am[mt], bh[nt]);
                mma8(accB[mt][nt], ah[mt], bm[nt]);
            }
    }

    __syncthreads();   // all warps done reading As/Bs (Cs overlays As)
    #pragma unroll
    for (int mt = 0; mt < 2; mt++)
        #pragma unroll
        for (int nt = 0; nt < 4; nt++) {
            int row = mrow + mt * 16 + lr;
            int col = ncol + nt * 8 + 2 * lc;
            float2 lo = make_float2(accA[mt][nt][0] + accB[mt][nt][0],
                                    accA[mt][nt][1] + accB[mt][nt][1]);
            float2 hi = make_float2(accA[mt][nt][2] + accB[mt][nt][2],
                                    accA[mt][nt][3] + accB[mt][nt][3]);
            *(float2*)&Cs[row * PAD + col] = lo;
            *(float2*)&Cs[(row + 8) * PAD + col] = hi;
        }
    __syncthreads();

    // --- row pass: top-8 per I-row over J-columns -> slot J ---
    for (int rr = w; rr < TILE; rr += 16) {
        float v[4];
        #pragma unroll
        for (int q = 0; q < 4; q++) v[q] = Cs[rr * PAD + lane + 32 * q];
        size_t grow = (size_t)b * NN + (size_t)I * TILE + rr;
        float* pv = g_pval + (grow * NT + J) * K_TOP;
        int*   pi = g_pidx + (grow * NT + J) * K_TOP;
        #pragma unroll
        for (int t = 0; t < K_TOP; t++) {
            float bv = v[0]; int bc = lane;
            #pragma unroll
            for (int q = 1; q < 4; q++) {
                int c = lane + 32 * q;
                if (v[q] > bv || (v[q] == bv && c < bc)) { bv = v[q]; bc = c; }
            }
            #pragma unroll
            for (int off = 16; off; off >>= 1) {
                float ov = __shfl_xor_sync(0xffffffffu, bv, off);
                int   oc = __shfl_xor_sync(0xffffffffu, bc, off);
                if (ov > bv || (ov == bv && oc < bc)) { bv = ov; bc = oc; }
            }
            if (lane == 0) { pv[t] = bv; pi[t] = J * TILE + bc; }
            if ((bc & 31) == lane) v[bc >> 5] = NEG_INF;
        }
    }

    // --- col pass (off-diagonal only) ---
    if (I != J) {
        for (int cc = w; cc < TILE; cc += 16) {
            float v[4];
            #pragma unroll
            for (int q = 0; q < 4; q++) v[q] = Cs[(lane + 32 * q) * PAD + cc];
            size_t grow = (size_t)b * NN + (size_t)J * TILE + cc;
            float* pv = g_pval + (grow * NT + I) * K_TOP;
            int*   pi = g_pidx + (grow * NT + I) * K_TOP;
            #pragma unroll
            for (int t = 0; t < K_TOP; t++) {
                float bv = v[0]; int br = lane;
                #pragma unroll
                for (int q = 1; q < 4; q++) {
                    int r = lane + 32 * q;
                    if (v[q] > bv || (v[q] == bv && r < br)) { bv = v[q]; br = r; }
                }
                #pragma unroll
                for (int off = 16; off; off >>= 1) {
                    float ov = __shfl_xor_sync(0xffffffffu, bv, off);
                    int   orr = __shfl_xor_sync(0xffffffffu, br, off);
                    if (ov > bv || (ov == bv && orr < br)) { bv = ov; br = orr; }
                }
                if (lane == 0) { pv[t] = bv; pi[t] = I * TILE + br; }
                if ((br & 31) == lane) v[br >> 5] = NEG_INF;
            }
        }
    }
}

// ---------------------------------------------------------------------------
__global__ void merge_scatter_kernel(float* __restrict__ out) {
    int gw   = (blockIdx.x * blockDim.x + threadIdx.x) >> 5;
    int lane = threadIdx.x & 31;
    if (gw >= BB * NN) return;
    int b = gw / NN, n = gw % NN;
    const float* pv = g_pval + (size_t)gw * NT * K_TOP;
    const int*   pi = g_pidx + (size_t)gw * NT * K_TOP;
    float v[4]; int id[4];
    #pragma unroll
    for (int q = 0; q < 4; q++) {
        v[q]  = pv[lane + 32 * q];
        id[q] = pi[lane + 32 * q];
    }
    float* base = out + (size_t)b * NN * NN;
    #pragma unroll
    for (int t = 0; t < K_TOP; t++) {
        float bv = v[0]; int bi = id[0];
        #pragma unroll
        for (int q = 1; q < 4; q++)
            if (v[q] > bv || (v[q] == bv && id[q] < bi)) { bv = v[q]; bi = id[q]; }
        #pragma unroll
        for (int off = 16; off; off >>= 1) {
            float ov = __shfl_xor_sync(0xffffffffu, bv, off);
            int   oi = __shfl_xor_sync(0xffffffffu, bi, off);
            if (ov > bv || (ov == bv && oi < bi)) { bv = ov; bi = oi; }
        }
        if (lane == t) {
            base[(size_t)n * NN + bi] = 1.0f;
            base[(size_t)bi * NN + n] = 1.0f;
        }
        #pragma unroll
        for (int q = 0; q < 4; q++)
            if (id[q] == bi) v[q] = NEG_INF;
    }
    if (lane == 8) base[(size_t)n * NN + n] = 1.0f;
}

// ---------------------------------------------------------------------------
extern "C" void kernel_launch(void* const* d_in, const int* in_sizes, int n_in,
                              void* d_out, int out_size) {
    const float* x = (const float*)d_in[0];
    float* out = (float*)d_out;

    int smem = 2 * TILE * PAD * 4;   // 135168
    cudaFuncSetAttribute(gemm_topk_kernel,
                         cudaFuncAttributeMaxDynamicSharedMemorySize, smem);

    normalize_kernel<<<(BB * NN) / 8, 256>>>(x);
    zero_kernel<<<8192, 256>>>((float4*)out, out_size / 4);
    gemm_topk_kernel<<<dim3(NT * (NT + 1) / 2, BB), 512, smem>>>();
    merge_scatter_kernel<<<(BB * NN) / 8, 256>>>(out);
}